// round 15
// baseline (speedup 1.0000x reference)
#include <cuda_runtime.h>
#include <cuda_fp16.h>
#include <cstdint>
#include <math.h>

// ----------------------------------------------------------------------------
// CrossModalAttention sm_103a — Round 13.
// cvt:  fp32 -> fp16 staging (unchanged).
// proj: fp16 GEMM re-tiled: 4 warps/CTA, warp tile 64x64 (crossbar halved).
// attn: R12 FA2 structure + ks rotation per warp + QK b double-buffer + ex2.
// ----------------------------------------------------------------------------

namespace {
constexpr int N_ = 2048;
constexpr int DIM = 512;
constexpr int H = 4;
constexpr int HD = 128;
constexpr int BM = 12;
constexpr int ROWS = BM * N_;                      // 24576
constexpr size_t XE = (size_t)ROWS * DIM;          // 12,582,912
constexpr size_t WE = (size_t)DIM * DIM;           // 262,144
constexpr float INV_SCALE = 0.08838834764831845f;  // 1/sqrt(128)
constexpr float EXC = 0.12751875731634632f;        // INV_SCALE * log2(e)
}

__device__ __half g_Xh[3 * XE];
__device__ __half g_Wh[3 * WE];
__device__ __half g_Qh[XE];
__device__ __half g_Kh[XE];
__device__ __half g_Vt[XE];  // V transposed per (bm,h): [(bm*H+h)*HD+d][n]

// ---------------------------------------------------------------- helpers
__device__ __forceinline__ void mma_f16(float* c, uint32_t a0, uint32_t a1,
                                        uint32_t a2, uint32_t a3, uint32_t b0,
                                        uint32_t b1) {
  asm volatile(
      "mma.sync.aligned.m16n8k16.row.col.f32.f16.f16.f32 "
      "{%0,%1,%2,%3}, {%4,%5,%6,%7}, {%8,%9}, {%0,%1,%2,%3};\n"
      : "+f"(c[0]), "+f"(c[1]), "+f"(c[2]), "+f"(c[3])
      : "r"(a0), "r"(a1), "r"(a2), "r"(a3), "r"(b0), "r"(b1));
}

__device__ __forceinline__ uint32_t f2h2(float lo, float hi) {
  uint32_t u;
  asm("cvt.rn.f16x2.f32 %0, %1, %2;" : "=r"(u) : "f"(hi), "f"(lo));
  return u;
}

__device__ __forceinline__ float ex2(float x) {
  float r;
  asm("ex2.approx.f32 %0, %1;" : "=f"(r) : "f"(x));
  return r;
}

__device__ __forceinline__ void cp16(uint32_t smem_addr, const void* gmem) {
  asm volatile("cp.async.cg.shared.global [%0], [%1], 16;\n" ::"r"(smem_addr),
               "l"(gmem));
}
__device__ __forceinline__ void cp_commit() {
  asm volatile("cp.async.commit_group;\n");
}
template <int N>
__device__ __forceinline__ void cp_wait() {
  asm volatile("cp.async.wait_group %0;\n" ::"n"(N));
}

// ----------------------------------------------------------------------------
// Convert kernel: fp32 inputs -> fp16 staging.
// ----------------------------------------------------------------------------
__global__ __launch_bounds__(256) void cvt_kernel(
    const float* __restrict__ q, const float* __restrict__ k,
    const float* __restrict__ v, const float* __restrict__ Wq,
    const float* __restrict__ Wk, const float* __restrict__ Wv) {
  const size_t base = ((size_t)blockIdx.x * 256 + threadIdx.x) * 4;
  const float* src;
  __half* dst;
  size_t off;
  if (base < 3 * XE) {
    const int t = (int)(base / XE);
    off = base - (size_t)t * XE;
    src = (t == 0) ? q : (t == 1) ? k : v;
    dst = g_Xh + (size_t)t * XE;
  } else {
    const size_t b2 = base - 3 * XE;
    const int t = (int)(b2 / WE);
    off = b2 - (size_t)t * WE;
    src = (t == 0) ? Wq : (t == 1) ? Wk : Wv;
    dst = g_Wh + (size_t)t * WE;
  }
  const float4 x = *(const float4*)(src + off);
  uint2 o;
  o.x = f2h2(x.x, x.y);
  o.y = f2h2(x.z, x.w);
  *(uint2*)(dst + off) = o;
}

// ----------------------------------------------------------------------------
// Projection: fp16 GEMM, block 128x128, 128 threads (4 warps 2m x 2n),
// warp tile 64x64 (Mt4, Nt8). BK=64 fp16, cp.async double-buffered.
// ----------------------------------------------------------------------------
namespace {
constexpr int PJ_X = 0;      // 2 x 4096 u32
constexpr int PJ_W = 8192;   // 2 x 4096 u32
constexpr int PROJ_SMEM_BYTES = 16384 * 4;  // 65536
}

__global__ __launch_bounds__(128, 2) void proj_kernel(
    const float* __restrict__ bq, const float* __restrict__ bk,
    const float* __restrict__ bv) {
  extern __shared__ uint32_t psm[];
  const uint32_t sbase = (uint32_t)__cvta_generic_to_shared(psm);

  const int z = blockIdx.z;
  const __half* X = g_Xh + (size_t)z * XE;
  const __half* W = g_Wh + (size_t)z * WE;
  const float* bias = (z == 0) ? bq : (z == 1) ? bk : bv;

  const int row0 = blockIdx.y * 128;
  const int col0 = blockIdx.x * 128;
  const int tid = threadIdx.x;
  const int wid = tid >> 5, lane = tid & 31;
  const int g = lane >> 2, tig = lane & 3;
  const int wm = wid & 1, wn = wid >> 1;
  const int sw = g << 2;

  // cp.async base slots: i-th (i<8) at +i*2048 bytes smem, +i*16*DIM gmem.
  const int r0l = tid >> 3;           // 0..15
  const int c4l = (tid & 7) * 4;      // 0..28
  const int scl = c4l ^ ((r0l & 7) << 2);
  const uint32_t xs0 = sbase + 4 * (PJ_X + r0l * 32 + scl);
  const uint32_t ws0 = sbase + 4 * (PJ_W + r0l * 32 + scl);
  const __half* xg0 = X + (size_t)(row0 + r0l) * DIM + c4l * 2;
  const __half* wg0 = W + (size_t)(col0 + r0l) * DIM + c4l * 2;

#pragma unroll
  for (int i = 0; i < 8; i++) {
    cp16(xs0 + i * 2048, xg0 + (size_t)i * 16 * DIM);
    cp16(ws0 + i * 2048, wg0 + (size_t)i * 16 * DIM);
  }
  cp_commit();

  float c[4][8][4] = {};

  for (int ch = 0; ch < 8; ch++) {
    __syncthreads();
    if (ch < 7) {
      const int k0 = (ch + 1) * 64;  // fp16 offset
      const uint32_t boff = ((ch + 1) & 1) * 16384;  // bytes
#pragma unroll
      for (int i = 0; i < 8; i++) {
        cp16(xs0 + boff + i * 2048, xg0 + (size_t)i * 16 * DIM + k0);
        cp16(ws0 + boff + i * 2048, wg0 + (size_t)i * 16 * DIM + k0);
      }
      cp_commit();
      cp_wait<1>();
    } else {
      cp_wait<0>();
    }
    __syncthreads();

    const uint32_t* Xs = psm + PJ_X + (ch & 1) * 4096;
    const uint32_t* Ws = psm + PJ_W + (ch & 1) * 4096;
#pragma unroll
    for (int ks = 0; ks < 4; ks++) {
      const int c0 = (ks * 8 + tig) ^ sw;
      const int c1 = (ks * 8 + tig + 4) ^ sw;
      uint32_t a[4][4], b[8][2];
#pragma unroll
      for (int mt = 0; mt < 4; mt++) {
        const uint32_t* p0 = Xs + (wm * 64 + mt * 16 + g) * 32;
        a[mt][0] = p0[c0];
        a[mt][1] = p0[256 + c0];
        a[mt][2] = p0[c1];
        a[mt][3] = p0[256 + c1];
      }
#pragma unroll
      for (int nt = 0; nt < 8; nt++) {
        const uint32_t* bp = Ws + (wn * 64 + nt * 8 + g) * 32;
        b[nt][0] = bp[c0];
        b[nt][1] = bp[c1];
      }
#pragma unroll
      for (int mt = 0; mt < 4; mt++)
#pragma unroll
        for (int nt = 0; nt < 8; nt++)
          mma_f16(c[mt][nt], a[mt][0], a[mt][1], a[mt][2], a[mt][3],
                  b[nt][0], b[nt][1]);
    }
  }

  // epilogue: bias add, store fp16 (V transposed per (bm,h))
#pragma unroll
  for (int nt = 0; nt < 8; nt++) {
    const int colp = col0 + wn * 64 + nt * 8 + 2 * tig;
    const float b0 = bias[colp], b1 = bias[colp + 1];
#pragma unroll
    for (int mt = 0; mt < 4; mt++) {
      const int r0 = row0 + wm * 64 + mt * 16 + g;
      const float v00 = c[mt][nt][0] + b0, v01 = c[mt][nt][1] + b1;
      const float v10 = c[mt][nt][2] + b0, v11 = c[mt][nt][3] + b1;
      if (z != 2) {
        __half* ob = (z == 0) ? g_Qh : g_Kh;
        *(uint32_t*)(ob + (size_t)r0 * DIM + colp) = f2h2(v00, v01);
        *(uint32_t*)(ob + (size_t)(r0 + 8) * DIM + colp) = f2h2(v10, v11);
      } else {
        const int bmz = r0 >> 11, n = r0 & 2047;
        const size_t dbase =
            ((size_t)(bmz * H + (colp >> 7)) * HD + (colp & 127)) * N_ + n;
        g_Vt[dbase] = __float2half_rn(v00);
        g_Vt[dbase + N_] = __float2half_rn(v01);
        g_Vt[dbase + 8] = __float2half_rn(v10);
        g_Vt[dbase + N_ + 8] = __float2half_rn(v11);
      }
    }
  }
}

// ----------------------------------------------------------------------------
// Flash attention — R12 FA2 structure + de-lockstep scheduling.
// 256 threads (8 warps), warp w owns q-rows [w*16, w*16+16) x ALL keys.
// ks iteration rotated per warp; QK b-frags register double-buffered.
// smem (u32): K 2x4096 | V 2x4096 -> 64KB.
// ----------------------------------------------------------------------------
namespace {
constexpr uint32_t AK = 0;
constexpr uint32_t AV = 8192;
constexpr uint32_t ATTN_SMEM_U32 = 16384;
constexpr uint32_t ATTN_SMEM_BYTES = ATTN_SMEM_U32 * 4;  // 65536
}

__global__ __launch_bounds__(256) void attn_kernel(float* __restrict__ out) {
  extern __shared__ uint32_t sm[];
  const uint32_t sbase = (uint32_t)__cvta_generic_to_shared(sm);

  const int tid = threadIdx.x;
  const int wid = tid >> 5, lane = tid & 31;
  const int g = lane >> 2, tig = lane & 3;
  const int sw = g << 2;

  const int bmh = blockIdx.y;
  const int h = bmh & 3, bm = bmh >> 2;
  const int q0 = blockIdx.x * 128;

  const __half* Kg = g_Kh + (size_t)(bm * N_) * DIM + h * HD;
  const __half* Vtg = g_Vt + (size_t)((bm * H + h) * HD) * N_;

  uint32_t kaddr[4];
  const __half* kg[4];
#pragma unroll
  for (int i = 0; i < 4; i++) {
    int id = tid + i * 256;
    int r = id >> 4, c4 = (id & 15) * 4;
    kaddr[i] = sbase + 4 * (AK + r * 64 + (c4 ^ ((r & 7) << 2)));
    kg[i] = Kg + (size_t)r * DIM + c4 * 2;
  }
  uint32_t vaddr[4];
  const __half* vg[4];
#pragma unroll
  for (int i = 0; i < 4; i++) {
    int id = tid + i * 256;
    int r = id >> 3, c4 = (id & 7) * 4;
    vaddr[i] = sbase + 4 * (AV + r * 32 + (c4 ^ ((r & 7) << 2)));
    vg[i] = Vtg + (size_t)r * N_ + c4 * 2;
  }

  // Q fragments register-cached (fp16, 32 u32)
  uint32_t aq[8][4];
  {
    const uint32_t* p0 = (const uint32_t*)(
        g_Qh + (size_t)(bm * N_ + q0 + wid * 16 + g) * DIM + h * HD);
    const uint32_t* p1 = (const uint32_t*)(
        g_Qh + (size_t)(bm * N_ + q0 + wid * 16 + g + 8) * DIM + h * HD);
#pragma unroll
    for (int ks = 0; ks < 8; ks++) {
      aq[ks][0] = __ldg(p0 + ks * 8 + tig);
      aq[ks][1] = __ldg(p1 + ks * 8 + tig);
      aq[ks][2] = __ldg(p0 + ks * 8 + tig + 4);
      aq[ks][3] = __ldg(p1 + ks * 8 + tig + 4);
    }
  }

  // prologue: K(0)+V(0)
#pragma unroll
  for (int i = 0; i < 4; i++) {
    cp16(kaddr[i], kg[i]);
    cp16(vaddr[i], vg[i]);
  }
  cp_commit();

  float o[16][4] = {};
  float lp[2] = {};

  for (int it = 0; it < 32; ++it) {
    cp_wait<0>();
    __syncthreads();

    if (it + 1 < 32) {
      const size_t kt1 = (size_t)(it + 1) * 64;
      const uint32_t boff = ((it + 1) & 1) * 16384;
#pragma unroll
      for (int i = 0; i < 4; i++) {
        cp16(kaddr[i] + boff, kg[i] + kt1 * DIM);
        cp16(vaddr[i] + boff, vg[i] + kt1);
      }
      cp_commit();
    }

    const uint32_t* Kc = sm + AK + (it & 1) * 4096;
    const uint32_t* Vs = sm + AV + (it & 1) * 4096;

    // ---- S = Q K^T — ks rotated per warp, b register-double-buffered ----
    float s[8][4] = {};
    uint32_t bb[2][8][2];
    {
      const int ks0 = wid & 7;
      const int c0 = (ks0 * 8 + tig) ^ sw;
      const int c1 = (ks0 * 8 + tig + 4) ^ sw;
#pragma unroll
      for (int nt = 0; nt < 8; nt++) {
        const uint32_t* bp = Kc + (nt * 8 + g) * 64;
        bb[0][nt][0] = bp[c0];
        bb[0][nt][1] = bp[c1];
      }
    }
#pragma unroll
    for (int ksi = 0; ksi < 8; ksi++) {
      const int cur = ksi & 1;
      if (ksi < 7) {
        const int ksn = (ksi + 1 + wid) & 7;
        const int c0 = (ksn * 8 + tig) ^ sw;
        const int c1 = (ksn * 8 + tig + 4) ^ sw;
#pragma unroll
        for (int nt = 0; nt < 8; nt++) {
          const uint32_t* bp = Kc + (nt * 8 + g) * 64;
          bb[cur ^ 1][nt][0] = bp[c0];
          bb[cur ^ 1][nt][1] = bp[c1];
        }
      }
      const int ksc = (ksi + wid) & 7;
#pragma unroll
      for (int nt = 0; nt < 8; nt++)
        mma_f16(s[nt], aq[ksc][0], aq[ksc][1], aq[ksc][2], aq[ksc][3],
                bb[cur][nt][0], bb[cur][nt][1]);
    }

    // ---- max-free softmax (ex2); P packed into PV A-fragments ----
    uint32_t pa[4][4];
#pragma unroll
    for (int nt = 0; nt < 8; nt++) {
      const float p0 = ex2(s[nt][0] * EXC);
      const float p1 = ex2(s[nt][1] * EXC);
      const float p2 = ex2(s[nt][2] * EXC);
      const float p3 = ex2(s[nt][3] * EXC);
      lp[0] += p0 + p1;
      lp[1] += p2 + p3;
      pa[nt >> 1][(nt & 1) * 2 + 0] = f2h2(p0, p1);
      pa[nt >> 1][(nt & 1) * 2 + 1] = f2h2(p2, p3);
    }

    // ---- O += P V — ks rotated per warp (SMSP pair desync via wid>>1) ----
#pragma unroll
    for (int ksi = 0; ksi < 4; ksi++) {
      const int ks = (ksi + (wid >> 1)) & 3;
      const int c0 = (ks * 8 + tig) ^ sw;
      const int c1 = (ks * 8 + tig + 4) ^ sw;
#pragma unroll
      for (int nt = 0; nt < 16; nt++) {
        const uint32_t* vp = Vs + (nt * 8 + g) * 32;
        mma_f16(o[nt], pa[ks][0], pa[ks][1], pa[ks][2], pa[ks][3], vp[c0],
                vp[c1]);
      }
    }
  }

  // ---- epilogue ----
  float l0 = lp[0], l1 = lp[1];
  l0 += __shfl_xor_sync(0xffffffffu, l0, 1);
  l0 += __shfl_xor_sync(0xffffffffu, l0, 2);
  l1 += __shfl_xor_sync(0xffffffffu, l1, 1);
  l1 += __shfl_xor_sync(0xffffffffu, l1, 2);
  const float il0 = 1.0f / l0;
  const float il1 = 1.0f / l1;

  const int row0 = wid * 16 + g;
#pragma unroll
  for (int nt = 0; nt < 16; nt++) {
    const int col = nt * 8 + 2 * tig;
    float* op = out + (size_t)(bm * N_ + q0 + row0) * DIM + h * HD + col;
    *(float2*)op = make_float2(o[nt][0] * il0, o[nt][1] * il0);
    *(float2*)(op + 8 * DIM) = make_float2(o[nt][2] * il1, o[nt][3] * il1);
  }
}

// ----------------------------------------------------------------------------
extern "C" void kernel_launch(void* const* d_in, const int* in_sizes, int n_in,
                              void* d_out, int out_size) {
  const float* q  = (const float*)d_in[0];
  const float* k  = (const float*)d_in[1];
  const float* v  = (const float*)d_in[2];
  const float* Wq = (const float*)d_in[3];
  const float* bq = (const float*)d_in[4];
  const float* Wk = (const float*)d_in[5];
  const float* bk = (const float*)d_in[6];
  const float* Wv = (const float*)d_in[7];
  const float* bv = (const float*)d_in[8];
  float* out = (float*)d_out;

  static bool attr_done = false;
  if (!attr_done) {
    cudaFuncSetAttribute(proj_kernel,
                         cudaFuncAttributeMaxDynamicSharedMemorySize,
                         PROJ_SMEM_BYTES);
    cudaFuncSetAttribute(attn_kernel,
                         cudaFuncAttributeMaxDynamicSharedMemorySize,
                         ATTN_SMEM_BYTES);
    attr_done = true;
  }

  const int cvt_blocks = (int)((3 * XE + 3 * WE) / 4 / 256);
  cvt_kernel<<<cvt_blocks, 256>>>(q, k, v, Wq, Wk, Wv);

  dim3 pgrid(DIM / 128, ROWS / 128, 3);
  proj_kernel<<<pgrid, 128, PROJ_SMEM_BYTES>>>(bq, bk, bv);

  dim3 agrid(N_ / 128, BM * H);
  attn_kernel<<<agrid, 256, ATTN_SMEM_BYTES>>>(out);
}

// round 17
// speedup vs baseline: 1.2186x; 1.2186x over previous
#include <cuda_runtime.h>
#include <cuda_fp16.h>
#include <cstdint>
#include <math.h>

// ----------------------------------------------------------------------------
// CrossModalAttention sm_103a — Round 14.
// cvt:  fp32 -> fp16 staging (unchanged, ~37us).
// proj: fp16 m16n8k16 GEMM — EXACT R9 version (proven ~115us).
// attn: R12 FA2 register-P structure with TK=128 (one change): halves loop
//       overhead, doubles mma train length. K/V double-buffered (128KB smem).
// ----------------------------------------------------------------------------

namespace {
constexpr int N_ = 2048;
constexpr int DIM = 512;
constexpr int H = 4;
constexpr int HD = 128;
constexpr int BM = 12;
constexpr int ROWS = BM * N_;                      // 24576
constexpr size_t XE = (size_t)ROWS * DIM;          // 12,582,912
constexpr size_t WE = (size_t)DIM * DIM;           // 262,144
constexpr float INV_SCALE = 0.08838834764831845f;  // 1/sqrt(128)
}

__device__ __half g_Xh[3 * XE];
__device__ __half g_Wh[3 * WE];
__device__ __half g_Qh[XE];
__device__ __half g_Kh[XE];
__device__ __half g_Vt[XE];  // V transposed per (bm,h): [(bm*H+h)*HD+d][n]

// ---------------------------------------------------------------- helpers
__device__ __forceinline__ void mma_f16(float* c, uint32_t a0, uint32_t a1,
                                        uint32_t a2, uint32_t a3, uint32_t b0,
                                        uint32_t b1) {
  asm volatile(
      "mma.sync.aligned.m16n8k16.row.col.f32.f16.f16.f32 "
      "{%0,%1,%2,%3}, {%4,%5,%6,%7}, {%8,%9}, {%0,%1,%2,%3};\n"
      : "+f"(c[0]), "+f"(c[1]), "+f"(c[2]), "+f"(c[3])
      : "r"(a0), "r"(a1), "r"(a2), "r"(a3), "r"(b0), "r"(b1));
}

__device__ __forceinline__ uint32_t f2h2(float lo, float hi) {
  uint32_t u;
  asm("cvt.rn.f16x2.f32 %0, %1, %2;" : "=r"(u) : "f"(hi), "f"(lo));
  return u;
}

__device__ __forceinline__ void cp16(uint32_t smem_addr, const void* gmem) {
  asm volatile("cp.async.cg.shared.global [%0], [%1], 16;\n" ::"r"(smem_addr),
               "l"(gmem));
}
__device__ __forceinline__ void cp_commit() {
  asm volatile("cp.async.commit_group;\n");
}
template <int N>
__device__ __forceinline__ void cp_wait() {
  asm volatile("cp.async.wait_group %0;\n" ::"n"(N));
}

// ----------------------------------------------------------------------------
// Convert kernel: fp32 inputs -> fp16 staging.
// ----------------------------------------------------------------------------
__global__ __launch_bounds__(256) void cvt_kernel(
    const float* __restrict__ q, const float* __restrict__ k,
    const float* __restrict__ v, const float* __restrict__ Wq,
    const float* __restrict__ Wk, const float* __restrict__ Wv) {
  const size_t base = ((size_t)blockIdx.x * 256 + threadIdx.x) * 4;
  const float* src;
  __half* dst;
  size_t off;
  if (base < 3 * XE) {
    const int t = (int)(base / XE);
    off = base - (size_t)t * XE;
    src = (t == 0) ? q : (t == 1) ? k : v;
    dst = g_Xh + (size_t)t * XE;
  } else {
    const size_t b2 = base - 3 * XE;
    const int t = (int)(b2 / WE);
    off = b2 - (size_t)t * WE;
    src = (t == 0) ? Wq : (t == 1) ? Wk : Wv;
    dst = g_Wh + (size_t)t * WE;
  }
  const float4 x = *(const float4*)(src + off);
  uint2 o;
  o.x = f2h2(x.x, x.y);
  o.y = f2h2(x.z, x.w);
  *(uint2*)(dst + off) = o;
}

// ----------------------------------------------------------------------------
// Projection: fp16 GEMM — EXACT R9 version.
// 256 thr, block 128x128, BK=64 fp16, cp.async 2-buf, 8 warps 2m x 4n.
// ----------------------------------------------------------------------------
namespace {
constexpr int PJ_X = 0;      // 2 x 4096 u32
constexpr int PJ_W = 8192;   // 2 x 4096 u32
constexpr int PROJ_SMEM_BYTES = 16384 * 4;  // 65536
}

__global__ __launch_bounds__(256, 2) void proj_kernel(
    const float* __restrict__ bq, const float* __restrict__ bk,
    const float* __restrict__ bv) {
  extern __shared__ uint32_t psm[];
  const uint32_t sbase = (uint32_t)__cvta_generic_to_shared(psm);

  const int z = blockIdx.z;
  const __half* X = g_Xh + (size_t)z * XE;
  const __half* W = g_Wh + (size_t)z * WE;
  const float* bias = (z == 0) ? bq : (z == 1) ? bk : bv;

  const int row0 = blockIdx.y * 128;
  const int col0 = blockIdx.x * 128;
  const int tid = threadIdx.x;
  const int wid = tid >> 5, lane = tid & 31;
  const int g = lane >> 2, tig = lane & 3;
  const int wm = wid & 1, wn = wid >> 1;
  const int sw = g << 2;

  uint32_t xs_addr[4], ws_addr[4];
  const __half* xg[4];
  const __half* wg[4];
#pragma unroll
  for (int i = 0; i < 4; i++) {
    const int id = tid + i * 256;
    const int r = id >> 3, c4 = (id & 7) * 4;
    const int sc = c4 ^ ((r & 7) << 2);
    xs_addr[i] = sbase + 4 * (PJ_X + r * 32 + sc);
    ws_addr[i] = sbase + 4 * (PJ_W + r * 32 + sc);
    xg[i] = X + (size_t)(row0 + r) * DIM + c4 * 2;
    wg[i] = W + (size_t)(col0 + r) * DIM + c4 * 2;
  }
#pragma unroll
  for (int i = 0; i < 4; i++) {
    cp16(xs_addr[i], xg[i]);
    cp16(ws_addr[i], wg[i]);
  }
  cp_commit();

  float c[4][4][4] = {};

  for (int ch = 0; ch < 8; ch++) {
    __syncthreads();
    if (ch < 7) {
      const int k0 = (ch + 1) * 64;
      const uint32_t boff = ((ch + 1) & 1) * 16384;
#pragma unroll
      for (int i = 0; i < 4; i++) {
        cp16(xs_addr[i] + boff, xg[i] + k0);
        cp16(ws_addr[i] + boff, wg[i] + k0);
      }
      cp_commit();
      cp_wait<1>();
    } else {
      cp_wait<0>();
    }
    __syncthreads();

    const uint32_t* Xs = psm + PJ_X + (ch & 1) * 4096;
    const uint32_t* Ws = psm + PJ_W + (ch & 1) * 4096;
#pragma unroll
    for (int ks = 0; ks < 4; ks++) {
      const int c0 = (ks * 8 + tig) ^ sw;
      const int c1 = (ks * 8 + tig + 4) ^ sw;
      uint32_t a[4][4], b[4][2];
#pragma unroll
      for (int mt = 0; mt < 4; mt++) {
        const uint32_t* p0 = Xs + (wm * 64 + mt * 16 + g) * 32;
        a[mt][0] = p0[c0];
        a[mt][1] = p0[256 + c0];
        a[mt][2] = p0[c1];
        a[mt][3] = p0[256 + c1];
      }
#pragma unroll
      for (int nt = 0; nt < 4; nt++) {
        const uint32_t* bp = Ws + (wn * 32 + nt * 8 + g) * 32;
        b[nt][0] = bp[c0];
        b[nt][1] = bp[c1];
      }
#pragma unroll
      for (int mt = 0; mt < 4; mt++)
#pragma unroll
        for (int nt = 0; nt < 4; nt++)
          mma_f16(c[mt][nt], a[mt][0], a[mt][1], a[mt][2], a[mt][3],
                  b[nt][0], b[nt][1]);
    }
  }

#pragma unroll
  for (int nt = 0; nt < 4; nt++) {
    const int colp = col0 + wn * 32 + nt * 8 + 2 * tig;
    const float b0 = bias[colp], b1 = bias[colp + 1];
#pragma unroll
    for (int mt = 0; mt < 4; mt++) {
      const int r0 = row0 + wm * 64 + mt * 16 + g;
      const float v00 = c[mt][nt][0] + b0, v01 = c[mt][nt][1] + b1;
      const float v10 = c[mt][nt][2] + b0, v11 = c[mt][nt][3] + b1;
      if (z != 2) {
        __half* ob = (z == 0) ? g_Qh : g_Kh;
        *(uint32_t*)(ob + (size_t)r0 * DIM + colp) = f2h2(v00, v01);
        *(uint32_t*)(ob + (size_t)(r0 + 8) * DIM + colp) = f2h2(v10, v11);
      } else {
        const int bmz = r0 >> 11, n = r0 & 2047;
        const size_t dbase =
            ((size_t)(bmz * H + (colp >> 7)) * HD + (colp & 127)) * N_ + n;
        g_Vt[dbase] = __float2half_rn(v00);
        g_Vt[dbase + N_] = __float2half_rn(v01);
        g_Vt[dbase + 8] = __float2half_rn(v10);
        g_Vt[dbase + N_ + 8] = __float2half_rn(v11);
      }
    }
  }
}

// ----------------------------------------------------------------------------
// Flash attention — FA2 register-P, TK=128.
// 256 threads (8 warps), warp w owns q-rows [w*16, w*16+16) x ALL 128 keys
// of the tile. 16 outer iterations. K/V double-buffered.
// smem (u32): K 2x8192 | V 2x8192 -> 128KB.
// ----------------------------------------------------------------------------
namespace {
constexpr uint32_t AK = 0;       // 2 x 8192 u32
constexpr uint32_t AV = 16384;   // 2 x 8192 u32
constexpr uint32_t ATTN_SMEM_U32 = 32768;
constexpr uint32_t ATTN_SMEM_BYTES = ATTN_SMEM_U32 * 4;  // 131072
}

__global__ __launch_bounds__(256) void attn_kernel(float* __restrict__ out) {
  extern __shared__ uint32_t sm[];
  const uint32_t sbase = (uint32_t)__cvta_generic_to_shared(sm);

  const int tid = threadIdx.x;
  const int wid = tid >> 5, lane = tid & 31;
  const int g = lane >> 2, tig = lane & 3;
  const int sw = g << 2;

  const int bmh = blockIdx.y;
  const int h = bmh & 3, bm = bmh >> 2;
  const int q0 = blockIdx.x * 128;

  const __half* Kg = g_Kh + (size_t)(bm * N_) * DIM + h * HD;
  const __half* Vtg = g_Vt + (size_t)((bm * H + h) * HD) * N_;

  // --- K cp.async slots: [128 key][64 u32], swizzle c^((r&7)<<2) ---
  uint32_t kaddr[8];
  const __half* kg[8];
#pragma unroll
  for (int i = 0; i < 8; i++) {
    int id = tid + i * 256;
    int r = id >> 4, c4 = (id & 15) * 4;
    kaddr[i] = sbase + 4 * (AK + r * 64 + (c4 ^ ((r & 7) << 2)));
    kg[i] = Kg + (size_t)r * DIM + c4 * 2;
  }
  // --- Vt cp.async slots: [128 dim][64 u32 = 128 keys], same swizzle ---
  uint32_t vaddr[8];
  const __half* vg[8];
#pragma unroll
  for (int i = 0; i < 8; i++) {
    int id = tid + i * 256;
    int r = id >> 4, c4 = (id & 15) * 4;
    vaddr[i] = sbase + 4 * (AV + r * 64 + (c4 ^ ((r & 7) << 2)));
    vg[i] = Vtg + (size_t)r * N_ + c4 * 2;
  }

  // --- Q fragments register-cached (fp16, 32 u32) ---
  uint32_t aq[8][4];
  {
    const uint32_t* p0 = (const uint32_t*)(
        g_Qh + (size_t)(bm * N_ + q0 + wid * 16 + g) * DIM + h * HD);
    const uint32_t* p1 = (const uint32_t*)(
        g_Qh + (size_t)(bm * N_ + q0 + wid * 16 + g + 8) * DIM + h * HD);
#pragma unroll
    for (int ks = 0; ks < 8; ks++) {
      aq[ks][0] = __ldg(p0 + ks * 8 + tig);
      aq[ks][1] = __ldg(p1 + ks * 8 + tig);
      aq[ks][2] = __ldg(p0 + ks * 8 + tig + 4);
      aq[ks][3] = __ldg(p1 + ks * 8 + tig + 4);
    }
  }

  // prologue: K(0)+V(0) -> one group
#pragma unroll
  for (int i = 0; i < 8; i++) {
    cp16(kaddr[i], kg[i]);
    cp16(vaddr[i], vg[i]);
  }
  cp_commit();

  float o[16][4] = {};
  float lp[2] = {};

  for (int it = 0; it < 16; ++it) {
    cp_wait<0>();     // K(it)/V(it) arrived
    __syncthreads();  // visibility + buffers (it+1)&1 free

    // issue K(it+1)+V(it+1)
    if (it + 1 < 16) {
      const size_t kt1 = (size_t)(it + 1) * 128;
      const uint32_t boff = ((it + 1) & 1) * 32768;
#pragma unroll
      for (int i = 0; i < 8; i++) {
        cp16(kaddr[i] + boff, kg[i] + kt1 * DIM);
        cp16(vaddr[i] + boff, vg[i] + kt1);
      }
      cp_commit();
    }

    const uint32_t* Kc = sm + AK + (it & 1) * 8192;
    const uint32_t* Vs = sm + AV + (it & 1) * 8192;

    // ---- S = Q K^T (warp rows x 128 keys: Nt16, 8 k16-steps) ----
    float s[16][4] = {};
#pragma unroll
    for (int ks = 0; ks < 8; ks++) {
      const int c0 = (ks * 8 + tig) ^ sw;
      const int c1 = (ks * 8 + tig + 4) ^ sw;
#pragma unroll
      for (int nt = 0; nt < 16; nt++) {
        const uint32_t* bp = Kc + (nt * 8 + g) * 64;
        mma_f16(s[nt], aq[ks][0], aq[ks][1], aq[ks][2], aq[ks][3], bp[c0],
                bp[c1]);
      }
    }

    // ---- max-free softmax; P packed into PV A-fragments ----
    uint32_t pa[8][4];
#pragma unroll
    for (int nt = 0; nt < 16; nt++) {
      const float p0 = __expf(s[nt][0] * INV_SCALE);
      const float p1 = __expf(s[nt][1] * INV_SCALE);
      const float p2 = __expf(s[nt][2] * INV_SCALE);
      const float p3 = __expf(s[nt][3] * INV_SCALE);
      lp[0] += p0 + p1;
      lp[1] += p2 + p3;
      pa[nt >> 1][(nt & 1) * 2 + 0] = f2h2(p0, p1);
      pa[nt >> 1][(nt & 1) * 2 + 1] = f2h2(p2, p3);
    }

    // ---- O += P V (warp rows x 128 dims: Nt16, 8 k16-steps) ----
#pragma unroll
    for (int ks = 0; ks < 8; ks++) {
      const int c0 = (ks * 8 + tig) ^ sw;
      const int c1 = (ks * 8 + tig + 4) ^ sw;
#pragma unroll
      for (int nt = 0; nt < 16; nt++) {
        const uint32_t* vp = Vs + (nt * 8 + g) * 64;
        mma_f16(o[nt], pa[ks][0], pa[ks][1], pa[ks][2], pa[ks][3], vp[c0],
                vp[c1]);
      }
    }
  }

  // ---- epilogue: quad-reduce l, normalize, store ----
  float l0 = lp[0], l1 = lp[1];
  l0 += __shfl_xor_sync(0xffffffffu, l0, 1);
  l0 += __shfl_xor_sync(0xffffffffu, l0, 2);
  l1 += __shfl_xor_sync(0xffffffffu, l1, 1);
  l1 += __shfl_xor_sync(0xffffffffu, l1, 2);
  const float il0 = 1.0f / l0;
  const float il1 = 1.0f / l1;

  const int row0 = wid * 16 + g;
#pragma unroll
  for (int nt = 0; nt < 16; nt++) {
    const int col = nt * 8 + 2 * tig;
    float* op = out + (size_t)(bm * N_ + q0 + row0) * DIM + h * HD + col;
    *(float2*)op = make_float2(o[nt][0] * il0, o[nt][1] * il0);
    *(float2*)(op + 8 * DIM) = make_float2(o[nt][2] * il1, o[nt][3] * il1);
  }
}

// ----------------------------------------------------------------------------
extern "C" void kernel_launch(void* const* d_in, const int* in_sizes, int n_in,
                              void* d_out, int out_size) {
  const float* q  = (const float*)d_in[0];
  const float* k  = (const float*)d_in[1];
  const float* v  = (const float*)d_in[2];
  const float* Wq = (const float*)d_in[3];
  const float* bq = (const float*)d_in[4];
  const float* Wk = (const float*)d_in[5];
  const float* bk = (const float*)d_in[6];
  const float* Wv = (const float*)d_in[7];
  const float* bv = (const float*)d_in[8];
  float* out = (float*)d_out;

  static bool attr_done = false;
  if (!attr_done) {
    cudaFuncSetAttribute(proj_kernel,
                         cudaFuncAttributeMaxDynamicSharedMemorySize,
                         PROJ_SMEM_BYTES);
    cudaFuncSetAttribute(attn_kernel,
                         cudaFuncAttributeMaxDynamicSharedMemorySize,
                         ATTN_SMEM_BYTES);
    attr_done = true;
  }

  const int cvt_blocks = (int)((3 * XE + 3 * WE) / 4 / 256);
  cvt_kernel<<<cvt_blocks, 256>>>(q, k, v, Wq, Wk, Wv);

  dim3 pgrid(DIM / 128, ROWS / 128, 3);
  proj_kernel<<<pgrid, 256, PROJ_SMEM_BYTES>>>(bq, bk, bv);

  dim3 agrid(N_ / 128, BM * H);
  attn_kernel<<<agrid, 256, ATTN_SMEM_BYTES>>>(out);
}